// round 16
// baseline (speedup 1.0000x reference)
#include <cuda_runtime.h>
#include <cuda_fp16.h>
#include <cstdint>
#include <cstddef>

#define Nn 100000
#define En 500000
#define HID 128
#define NH 8
#define DKv 16
#define DFFv 512
#define WA_COLS 640
#define WB_COLS 384
#define SCAN_TB 1024
#define SCAN_NBLK ((Nn + SCAN_TB - 1) / SCAN_TB)

// ---------------- scratch (device globals; allocation-free) ----------------
__device__ __half g_qA[(size_t)Nn * HID];
__device__ __half g_qB[(size_t)Nn * HID];
__device__ __half g_kp[3][(size_t)Nn * HID];
__device__ __half g_vp[3][(size_t)Nn * HID];
__device__ float g_t[2][(size_t)Nn * HID];
__device__ float g_x[2][(size_t)Nn * HID];
__device__ float g_ff[2][(size_t)Nn * DFFv];
__device__ float g_hr[2][(size_t)Nn * HID];        // rounded copies of h_a/h_b
__device__ int g_cnt[Nn];
__device__ int g_incl[Nn];
__device__ int g_tsum[SCAN_NBLK];
__device__ int g_toff[SCAN_NBLK];
__device__ int g_off[3][Nn + 1];
__device__ int g_off2[3][Nn];
__device__ int g_csr[3][En];
__device__ float g_wA[(HID + 1) * WA_COLS];        // row 128 = bias (unrounded)
__device__ float g_wB[(HID + 1) * WB_COLS];
__device__ float g_war[2 * HID * HID];             // rounded Wa
__device__ float g_w1r[2 * HID * DFFv];            // rounded W1
__device__ float g_w2r[2 * DFFv * HID];            // rounded W2
__device__ int g_is64;

struct OutSegs { float* p[5]; };

// ---------------- helpers ----------------
__device__ __forceinline__ uint32_t f2tf32(float x) {
    uint32_t u;
    asm("cvt.rna.tf32.f32 %0, %1;" : "=r"(u) : "f"(x));
    return u;
}
__device__ __forceinline__ float roundtf(float x) {
    return __uint_as_float(f2tf32(x));
}
__device__ __forceinline__ int ldidx(const void* p, int i) {
    return g_is64 ? (int)((const long long*)p)[i] : ((const int*)p)[i];
}
__device__ __forceinline__ float4 ldh4(const __half* p) {
    uint2 r = *reinterpret_cast<const uint2*>(p);
    __half2 h0 = *reinterpret_cast<__half2*>(&r.x);
    __half2 h1 = *reinterpret_cast<__half2*>(&r.y);
    float2 f0 = __half22float2(h0), f1 = __half22float2(h1);
    return make_float4(f0.x, f0.y, f1.x, f1.y);
}

__global__ void fill_i32(int* p, int v, int n) {
    int i = blockIdx.x * blockDim.x + threadIdx.x;
    if (i < n) p[i] = v;
}
__global__ void round_copy_kernel(const float* __restrict__ src, float* __restrict__ dst, int n) {
    int i = blockIdx.x * blockDim.x + threadIdx.x;
    if (i < n) dst[i] = roundtf(src[i]);
}

// Detect whether index buffers are int64 (odd 32-bit words == 0) or int32.
__global__ void detect_kernel(const unsigned* __restrict__ p) {
    if (blockIdx.x == 0 && threadIdx.x == 0) {
        int any = 0;
        for (int i = 1; i < 2048; i += 2) any |= (p[i] != 0u);
        g_is64 = !any;
    }
}

// ---------------- weight fusion prep (rounded weights, raw bias row) ----------------
__global__ void build_weights_kernel(
    const float* __restrict__ Wk, const float* __restrict__ bk,
    const float* __restrict__ Wq, const float* __restrict__ bq,
    const float* __restrict__ Wv, const float* __restrict__ bv,
    const float* __restrict__ att, const float* __restrict__ msg)
{
    int idx = blockIdx.x * blockDim.x + threadIdx.x;
    int total = (HID + 1) * (WA_COLS + WB_COLS);
    if (idx >= total) return;
    int isB = idx >= (HID + 1) * WA_COLS;
    int rem = isB ? idx - (HID + 1) * WA_COLS : idx;
    int cols = isB ? WB_COLS : WA_COLS;
    int i = rem / cols;          // 0..128 (128 = bias row)
    int c = rem % cols;
    int seg = c >> 7;
    int cl = c & 127;
    int h = cl >> 4, j = cl & 15;
    int ty = isB ? 1 : 0;
    float out;
    if (seg == 0) {
        out = (i < HID) ? Wq[((size_t)ty * HID + i) * HID + cl] : bq[ty * HID + cl];
    } else {
        int r = isB ? 1 : (seg <= 2 ? 0 : 2);
        int isV = (seg & 1) == 0;
        const float* W = isV ? Wv : Wk;
        const float* bb = isV ? bv : bk;
        const float* T = isV ? msg : att;
        const float* Th = T + ((size_t)(r * NH + h) * DKv) * DKv + j;
        float acc = 0.f;
        if (i < HID) {
            const float* Wr = W + ((size_t)ty * HID + i) * HID + h * DKv;
#pragma unroll
            for (int l = 0; l < DKv; l++) acc += Wr[l] * Th[(size_t)l * DKv];
        } else {
            const float* br = bb + ty * HID + h * DKv;
#pragma unroll
            for (int l = 0; l < DKv; l++) acc += br[l] * Th[(size_t)l * DKv];
        }
        out = acc;
    }
    if (i < HID) out = roundtf(out);
    if (isB) g_wB[(size_t)i * WB_COLS + c] = out;
    else     g_wA[(size_t)i * WA_COLS + c] = out;
}

// ---------------- TF32 GEMM: cp.async double-buffered; ldmatrix A frags ----------------
#define LDA 36
#define LDB 136
#define A_WORDS (128 * LDA)
#define B_WORDS (32 * LDB)
#define GEMM_SMEM_BYTES ((2 * (A_WORDS + B_WORDS)) * 4)

__device__ __forceinline__ void cp16(uint32_t dst, const void* src, bool valid) {
    int sz = valid ? 16 : 0;
    asm volatile("cp.async.cg.shared.global [%0], [%1], 16, %2;"
                 :: "r"(dst), "l"(src), "r"(sz) : "memory");
}
#define CP_COMMIT() asm volatile("cp.async.commit_group;" ::: "memory")
#define CP_WAIT(n)  asm volatile("cp.async.wait_group %0;" :: "n"(n) : "memory")

__global__ __launch_bounds__(256) void tf32gemm_kernel(
    const float* __restrict__ A, const float* __restrict__ B,
    const float* __restrict__ bias, const float* __restrict__ res,
    OutSegs segs, int segStride, int M, int K, int Nc,
    int reluOut, int roundOut, int halfOut)
{
    extern __shared__ uint32_t smem[];
    uint32_t sbase = (uint32_t)__cvta_generic_to_shared(smem);

    int tid = threadIdx.x;
    int warp = tid >> 5, lane = tid & 31;
    int g = lane >> 2, t = lane & 3;
    int wm = warp >> 2, wn = warp & 3;
    int rowTile = blockIdx.y * 128;
    int colTile = blockIdx.x * 128;
    float* Cb = segs.p[blockIdx.x];

    float c[4][4][4];
#pragma unroll
    for (int m = 0; m < 4; m++)
#pragma unroll
        for (int n = 0; n < 4; n++)
#pragma unroll
            for (int r = 0; r < 4; r++) c[m][n][r] = 0.f;

    int arow = tid >> 3;
    int acol4 = (tid & 7) * 4;
    int brow = tid >> 3;
    int bcol4 = (tid & 7) * 4;

    // ldmatrix lane address component for A fragments:
    // matrix j = lane/8: j&1 -> +8 rows, j>>1 -> +4 k-cols; row within matrix = lane%8
    int aFragPart = (wm * 64 + (lane & 7) + ((lane >> 3) & 1) * 8) * LDA + ((lane >> 4) << 2);

    auto issueTile = [&](int k0, int buf) {
        uint32_t aBase = sbase + (uint32_t)buf * A_WORDS * 4;
        uint32_t bBase = sbase + (2 * A_WORDS + (uint32_t)buf * B_WORDS) * 4;
#pragma unroll
        for (int p = 0; p < 4; p++) {
            int r = arow + 32 * p;
            int gr = rowTile + r;
            cp16(aBase + (uint32_t)(r * LDA + acol4) * 4,
                 A + (size_t)gr * K + k0 + acol4, gr < M);
            int cc = bcol4 + 32 * p;
            cp16(bBase + (uint32_t)(brow * LDB + cc) * 4,
                 B + (size_t)(k0 + brow) * Nc + colTile + cc, true);
        }
    };

    int nit = K >> 5;
    issueTile(0, 0);
    CP_COMMIT();

    int cur = 0;
    for (int i = 0; i < nit; i++) {
        if (i + 1 < nit) {
            issueTile((i + 1) << 5, cur ^ 1);
            CP_COMMIT();
            CP_WAIT(1);
        } else {
            CP_WAIT(0);
        }
        __syncthreads();

        uint32_t aFragBase = sbase + ((uint32_t)cur * A_WORDS + (uint32_t)aFragPart) * 4;
        const uint32_t* Bc = smem + 2 * A_WORDS + (size_t)cur * B_WORDS;
#pragma unroll
        for (int ks = 0; ks < 32; ks += 8) {
            uint32_t a[4][4], b[4][2];
#pragma unroll
            for (int m = 0; m < 4; m++) {
                uint32_t addr = aFragBase + (uint32_t)(m * 16 * LDA + ks) * 4;
                asm volatile(
                    "ldmatrix.sync.aligned.m8n8.x4.shared.b16 {%0,%1,%2,%3}, [%4];"
                    : "=r"(a[m][0]), "=r"(a[m][1]), "=r"(a[m][2]), "=r"(a[m][3])
                    : "r"(addr));
            }
#pragma unroll
            for (int n = 0; n < 4; n++) {
                int cc = wn * 32 + n * 8 + g;
                b[n][0] = Bc[(ks + t) * LDB + cc];
                b[n][1] = Bc[(ks + t + 4) * LDB + cc];
            }
#pragma unroll
            for (int m = 0; m < 4; m++)
#pragma unroll
                for (int n = 0; n < 4; n++) {
                    asm volatile(
                        "mma.sync.aligned.m16n8k8.row.col.f32.tf32.tf32.f32 "
                        "{%0,%1,%2,%3}, {%4,%5,%6,%7}, {%8,%9}, {%0,%1,%2,%3};"
                        : "+f"(c[m][n][0]), "+f"(c[m][n][1]),
                          "+f"(c[m][n][2]), "+f"(c[m][n][3])
                        : "r"(a[m][0]), "r"(a[m][1]), "r"(a[m][2]), "r"(a[m][3]),
                          "r"(b[n][0]), "r"(b[n][1]));
                }
        }
        __syncthreads();
        cur ^= 1;
    }

#pragma unroll
    for (int m = 0; m < 4; m++) {
        int row0 = rowTile + wm * 64 + m * 16 + g;
#pragma unroll
        for (int n = 0; n < 4; n++) {
            int cws = wn * 32 + n * 8 + 2 * t;
            int col = colTile + cws;
            float b0 = bias[col], b1 = bias[col + 1];
#pragma unroll
            for (int h = 0; h < 2; h++) {
                int row = row0 + 8 * h;
                if (row >= M) continue;
                size_t off = (size_t)row * segStride + cws;
                float v0 = c[m][n][2 * h + 0] + b0;
                float v1 = c[m][n][2 * h + 1] + b1;
                if (halfOut) {
                    __half2 hv = __floats2half2_rn(v0, v1);
                    *reinterpret_cast<__half2*>(reinterpret_cast<__half*>(Cb) + off) = hv;
                } else {
                    if (res) { v0 += res[off]; v1 += res[off + 1]; }
                    if (reluOut) { v0 = fmaxf(v0, 0.f); v1 = fmaxf(v1, 0.f); }
                    if (roundOut) { v0 = roundtf(v0); v1 = roundtf(v1); }
                    *reinterpret_cast<float2*>(Cb + off) = make_float2(v0, v1);
                }
            }
        }
    }
}

// ---------------- CSR build (coalesced 3-phase scan) ----------------
__global__ void hist_kernel(const void* __restrict__ dst, int* __restrict__ cnt, int E) {
    int i = blockIdx.x * blockDim.x + threadIdx.x;
    if (i < E) atomicAdd(&cnt[ldidx(dst, i)], 1);
}

__global__ __launch_bounds__(SCAN_TB) void scan1_kernel(
    const int* __restrict__ cnt, int* __restrict__ incl, int* __restrict__ tsum, int Nv)
{
    __shared__ int sh[SCAN_TB];
    int i = blockIdx.x * SCAN_TB + threadIdx.x;
    int v = (i < Nv) ? cnt[i] : 0;
    sh[threadIdx.x] = v;
    __syncthreads();
#pragma unroll
    for (int d = 1; d < SCAN_TB; d <<= 1) {
        int u = (threadIdx.x >= d) ? sh[threadIdx.x - d] : 0;
        __syncthreads();
        sh[threadIdx.x] += u;
        __syncthreads();
    }
    if (i < Nv) incl[i] = sh[threadIdx.x];
    if (threadIdx.x == SCAN_TB - 1) tsum[blockIdx.x] = sh[SCAN_TB - 1];
}

__global__ __launch_bounds__(128) void scan2_kernel(
    const int* __restrict__ tsum, int* __restrict__ toff, int nb)
{
    __shared__ int sh[SCAN_NBLK];
    if (threadIdx.x == 0) {
        int run = 0;
        for (int b = 0; b < nb; b++) { sh[b] = run; run += tsum[b]; }
    }
    __syncthreads();
    for (int b = threadIdx.x; b < nb; b += 128) toff[b] = sh[b];
}

__global__ void scan3_kernel(
    const int* __restrict__ cnt, const int* __restrict__ incl,
    const int* __restrict__ toff, int* __restrict__ off, int* __restrict__ off2,
    int Nv, int Etot)
{
    int i = blockIdx.x * blockDim.x + threadIdx.x;
    if (i < Nv) {
        int e = toff[i >> 10] + incl[i] - cnt[i];
        off[i] = e;
        off2[i] = e;
    }
    if (i == 0) off[Nv] = Etot;
}

__global__ void scatter_kernel(const void* __restrict__ src, const void* __restrict__ dst,
                               int* __restrict__ off2, int* __restrict__ csr, int E) {
    int i = blockIdx.x * blockDim.x + threadIdx.x;
    if (i >= E) return;
    int pos = atomicAdd(&off2[ldidx(dst, i)], 1);
    csr[pos] = ldidx(src, i);
}

// ---------------- single-relation attention (fp16 operands), relu+round out ----------------
__global__ __launch_bounds__(256) void node_attn_kernel(
    const __half* __restrict__ KP, const __half* __restrict__ VP,
    const __half* __restrict__ Q,
    const int* __restrict__ off, const int* __restrict__ csr,
    const float* __restrict__ pri,
    float* __restrict__ T, int Nv)
{
    int node = (blockIdx.x * blockDim.x + threadIdx.x) >> 5;
    int lane = threadIdx.x & 31;
    if (node >= Nv) return;
    int h = lane >> 2;
    float prih = pri[h] * 0.25f;

    float4 q = ldh4(Q + (size_t)node * HID + lane * 4);
    int s0 = off[node], s1 = off[node + 1];

    float m = -3.4e38f, z = 0.f;
    float4 acc = make_float4(0.f, 0.f, 0.f, 0.f);

    for (int slot = s0; slot < s1; slot++) {
        int sa = csr[slot];
        float4 ka = ldh4(KP + (size_t)sa * HID + lane * 4);
        float4 va = ldh4(VP + (size_t)sa * HID + lane * 4);
        float pa = q.x * ka.x + q.y * ka.y + q.z * ka.z + q.w * ka.w;
        pa += __shfl_xor_sync(0xffffffffu, pa, 1);
        pa += __shfl_xor_sync(0xffffffffu, pa, 2);
        float sca = pa * prih;
        float mn = fmaxf(m, sca);
        float corr = __expf(m - mn);
        float ea = __expf(sca - mn);
        z = z * corr + ea;
        acc.x = acc.x * corr + va.x * ea;
        acc.y = acc.y * corr + va.y * ea;
        acc.z = acc.z * corr + va.z * ea;
        acc.w = acc.w * corr + va.w * ea;
        m = mn;
    }
    float inv = (z > 0.f) ? (1.f / z) : 0.f;
    float* tp = T + (size_t)node * HID + lane * 4;
    float4 o;
    o.x = roundtf(fmaxf(acc.x * inv, 0.f));
    o.y = roundtf(fmaxf(acc.y * inv, 0.f));
    o.z = roundtf(fmaxf(acc.z * inv, 0.f));
    o.w = roundtf(fmaxf(acc.w * inv, 0.f));
    *reinterpret_cast<float4*>(tp) = o;
}

// ---------------- dual-relation attention: r1 + r2 -> relu(round(sum)) ----------------
__global__ __launch_bounds__(256) void node_attn_dual_kernel(
    const __half* __restrict__ KP1, const __half* __restrict__ VP1,
    const __half* __restrict__ KP2, const __half* __restrict__ VP2,
    const __half* __restrict__ Q,
    const int* __restrict__ off1, const int* __restrict__ csr1,
    const int* __restrict__ off2, const int* __restrict__ csr2,
    const float* __restrict__ pri1, const float* __restrict__ pri2,
    float* __restrict__ T, int Nv)
{
    int node = (blockIdx.x * blockDim.x + threadIdx.x) >> 5;
    int lane = threadIdx.x & 31;
    if (node >= Nv) return;
    int h = lane >> 2;

    float4 q = ldh4(Q + (size_t)node * HID + lane * 4);
    float4 tot = make_float4(0.f, 0.f, 0.f, 0.f);

    {
        float prih = pri1[h] * 0.25f;
        int s0 = off1[node], s1 = off1[node + 1];
        float m = -3.4e38f, z = 0.f;
        float4 acc = make_float4(0.f, 0.f, 0.f, 0.f);
        for (int slot = s0; slot < s1; slot++) {
            int sa = csr1[slot];
            float4 ka = ldh4(KP1 + (size_t)sa * HID + lane * 4);
            float4 va = ldh4(VP1 + (size_t)sa * HID + lane * 4);
            float pa = q.x * ka.x + q.y * ka.y + q.z * ka.z + q.w * ka.w;
            pa += __shfl_xor_sync(0xffffffffu, pa, 1);
            pa += __shfl_xor_sync(0xffffffffu, pa, 2);
            float sca = pa * prih;
            float mn = fmaxf(m, sca);
            float corr = __expf(m - mn);
            float ea = __expf(sca - mn);
            z = z * corr + ea;
            acc.x = acc.x * corr + va.x * ea;
            acc.y = acc.y * corr + va.y * ea;
            acc.z = acc.z * corr + va.z * ea;
            acc.w = acc.w * corr + va.w * ea;
            m = mn;
        }
        float inv = (z > 0.f) ? (1.f / z) : 0.f;
        tot.x += acc.x * inv; tot.y += acc.y * inv;
        tot.z += acc.z * inv; tot.w += acc.w * inv;
    }
    {
        float prih = pri2[h] * 0.25f;
        int s0 = off2[node], s1 = off2[node + 1];
        float m = -3.4e38f, z = 0.f;
        float4 acc = make_float4(0.f, 0.f, 0.f, 0.f);
        for (int slot = s0; slot < s1; slot++) {
            int sa = csr2[slot];
            float4 ka = ldh4(KP2 + (size_t)sa * HID + lane * 4);
            float4 va = ldh4(VP2 + (size_t)sa * HID + lane * 4);
            float pa = q.x * ka.x + q.y * ka.y + q.z * ka.z + q.w * ka.w;
            pa += __shfl_xor_sync(0xffffffffu, pa, 1);
            pa += __shfl_xor_sync(0xffffffffu, pa, 2);
            float sca = pa * prih;
            float mn = fmaxf(m, sca);
            float corr = __expf(m - mn);
            float ea = __expf(sca - mn);
            z = z * corr + ea;
            acc.x = acc.x * corr + va.x * ea;
            acc.y = acc.y * corr + va.y * ea;
            acc.z = acc.z * corr + va.z * ea;
            acc.w = acc.w * corr + va.w * ea;
            m = mn;
        }
        float inv = (z > 0.f) ? (1.f / z) : 0.f;
        tot.x += acc.x * inv; tot.y += acc.y * inv;
        tot.z += acc.z * inv; tot.w += acc.w * inv;
    }

    float* tp = T + (size_t)node * HID + lane * 4;
    float4 o;
    o.x = roundtf(fmaxf(tot.x, 0.f));
    o.y = roundtf(fmaxf(tot.y, 0.f));
    o.z = roundtf(fmaxf(tot.z, 0.f));
    o.w = roundtf(fmaxf(tot.w, 0.f));
    *reinterpret_cast<float4*>(tp) = o;
}

// ---------------- LayerNorm over 128 (warp per row, in-place, rounded output) ----------------
__global__ __launch_bounds__(256) void ln_kernel(
    float* __restrict__ X, const float* __restrict__ gamma,
    const float* __restrict__ beta, int M)
{
    int warp = (blockIdx.x * blockDim.x + threadIdx.x) >> 5;
    int lane = threadIdx.x & 31;
    if (warp >= M) return;
    float4 v = *reinterpret_cast<float4*>(X + (size_t)warp * HID + lane * 4);
    float sum = v.x + v.y + v.z + v.w;
    float sq = v.x * v.x + v.y * v.y + v.z * v.z + v.w * v.w;
#pragma unroll
    for (int o = 16; o > 0; o >>= 1) {
        sum += __shfl_xor_sync(0xffffffffu, sum, o);
        sq += __shfl_xor_sync(0xffffffffu, sq, o);
    }
    float mu = sum * (1.f / 128.f);
    float var = sq * (1.f / 128.f) - mu * mu;
    float inv = rsqrtf(var + 1e-5f);
    float4 g = *reinterpret_cast<const float4*>(gamma + lane * 4);
    float4 b = *reinterpret_cast<const float4*>(beta + lane * 4);
    v.x = roundtf((v.x - mu) * inv * g.x + b.x);
    v.y = roundtf((v.y - mu) * inv * g.y + b.y);
    v.z = roundtf((v.z - mu) * inv * g.z + b.z);
    v.w = roundtf((v.w - mu) * inv * g.w + b.w);
    *reinterpret_cast<float4*>(X + (size_t)warp * HID + lane * 4) = v;
}

// ---------------- host ----------------
static void sgemm_seg(const float* A, const float* B, const float* bias, const float* res,
                      OutSegs segs, int segStride, int M, int K, int Nc,
                      int reluOut, int roundOut, int halfOut, cudaStream_t st)
{
    dim3 grid(Nc / 128, (M + 127) / 128);
    tf32gemm_kernel<<<grid, 256, GEMM_SMEM_BYTES, st>>>(
        A, B, bias, res, segs, segStride, M, K, Nc, reluOut, roundOut, halfOut);
}

template <typename T>
static T* symaddr(const void* sym) {
    void* p = nullptr;
    cudaGetSymbolAddress(&p, sym);
    return (T*)p;
}

extern "C" void kernel_launch(void* const* d_in, const int* in_sizes, int n_in,
                              void* d_out, int out_size)
{
    const float* h_a  = (const float*)d_in[0];
    const float* h_b  = (const float*)d_in[1];
    const float* Wk   = (const float*)d_in[2];
    const float* bk   = (const float*)d_in[3];
    const float* Wq   = (const float*)d_in[4];
    const float* bq   = (const float*)d_in[5];
    const float* Wv   = (const float*)d_in[6];
    const float* bv   = (const float*)d_in[7];
    const float* Wa   = (const float*)d_in[8];
    const float* ba   = (const float*)d_in[9];
    const float* gam  = (const float*)d_in[10];
    const float* bet  = (const float*)d_in[11];
    const float* W1   = (const float*)d_in[12];
    const float* b1   = (const float*)d_in[13];
    const float* W2   = (const float*)d_in[14];
    const float* b2   = (const float*)d_in[15];
    const float* pri  = (const float*)d_in[16];
    const float* ratt = (const float*)d_in[17];
    const float* rmsg = (const float*)d_in[18];

    int M = in_sizes[0] / HID;
    int Ec[3] = { in_sizes[19], in_sizes[21], in_sizes[23] };
    float* out = (float*)d_out;

    __half* qA = symaddr<__half>(&g_qA);
    __half* qB = symaddr<__half>(&g_qB);
    __half* kpB = symaddr<__half>(&g_kp);
    __half* vpB = symaddr<__half>(&g_vp);
    __half* kp[3] = { kpB, kpB + (size_t)Nn * HID, kpB + 2 * (size_t)Nn * HID };
    __half* vp[3] = { vpB, vpB + (size_t)Nn * HID, vpB + 2 * (size_t)Nn * HID };
    float* t0 = symaddr<float>(&g_t);  float* t1 = t0 + (size_t)Nn * HID;
    float* Xb = symaddr<float>(&g_x);
    float* FFb = symaddr<float>(&g_ff);
    float* X[2]  = { Xb, Xb + (size_t)Nn * HID };
    float* FF[2] = { FFb, FFb + (size_t)Nn * DFFv };
    float* hrB = symaddr<float>(&g_hr);
    float* hr[2] = { hrB, hrB + (size_t)Nn * HID };
    int* cnt  = symaddr<int>(&g_cnt);
    int* incl = symaddr<int>(&g_incl);
    int* tsum = symaddr<int>(&g_tsum);
    int* toff = symaddr<int>(&g_toff);
    int* offB = symaddr<int>(&g_off);
    int* off2B = symaddr<int>(&g_off2);
    int* csrB = symaddr<int>(&g_csr);
    int* off[3]  = { offB, offB + (Nn + 1), offB + 2 * (Nn + 1) };
    int* off2[3] = { off2B, off2B + Nn, off2B + 2 * Nn };
    int* csr[3]  = { csrB, csrB + En, csrB + 2 * En };
    float* wA = symaddr<float>(&g_wA);
    float* wB = symaddr<float>(&g_wB);
    float* war = symaddr<float>(&g_war);
    float* w1r = symaddr<float>(&g_w1r);
    float* w2r = symaddr<float>(&g_w2r);

    static cudaStream_t s1 = nullptr, s2 = nullptr;
    static cudaEvent_t evF = nullptr, evJ = nullptr, evG = nullptr, evE = nullptr;
    static cudaEvent_t evP = nullptr, evB = nullptr;
    if (!s1) {
        cudaStreamCreateWithFlags(&s1, cudaStreamNonBlocking);
        cudaStreamCreateWithFlags(&s2, cudaStreamNonBlocking);
        cudaEventCreateWithFlags(&evF, cudaEventDisableTiming);
        cudaEventCreateWithFlags(&evJ, cudaEventDisableTiming);
        cudaEventCreateWithFlags(&evG, cudaEventDisableTiming);
        cudaEventCreateWithFlags(&evE, cudaEventDisableTiming);
        cudaEventCreateWithFlags(&evP, cudaEventDisableTiming);
        cudaEventCreateWithFlags(&evB, cudaEventDisableTiming);
        cudaFuncSetAttribute(tf32gemm_kernel,
                             cudaFuncAttributeMaxDynamicSharedMemorySize,
                             GEMM_SMEM_BYTES);
    }

    // ---- detect idx dtype, then fork CSR build immediately on s1 ----
    detect_kernel<<<1, 32>>>((const unsigned*)d_in[19]);
    cudaEventRecord(evF, 0);
    cudaStreamWaitEvent(s1, evF, 0);
    for (int r = 0; r < 3; r++) {
        int E = Ec[r];
        fill_i32<<<(Nn + 255) / 256, 256, 0, s1>>>(cnt, 0, Nn);
        hist_kernel<<<(E + 255) / 256, 256, 0, s1>>>(d_in[20 + 2 * r], cnt, E);
        scan1_kernel<<<SCAN_NBLK, SCAN_TB, 0, s1>>>(cnt, incl, tsum, M);
        scan2_kernel<<<1, 128, 0, s1>>>(tsum, toff, (M + SCAN_TB - 1) / SCAN_TB);
        scan3_kernel<<<(Nn + 255) / 256, 256, 0, s1>>>(cnt, incl, toff, off[r], off2[r], M, E);
        scatter_kernel<<<(E + 255) / 256, 256, 0, s1>>>(d_in[19 + 2 * r], d_in[20 + 2 * r], off2[r], csr[r], E);
        if (r == 2) cudaEventRecord(evJ, s1);
    }

    // ---- rounded operand prep + fused weight build (default) ----
    {
        int nh = M * HID;
        round_copy_kernel<<<(nh + 255) / 256, 256>>>(h_a, hr[0], nh);
        round_copy_kernel<<<(nh + 255) / 256, 256>>>(h_b, hr[1], nh);
        round_copy_kernel<<<(2 * HID * HID + 255) / 256, 256>>>(Wa, war, 2 * HID * HID);
        round_copy_kernel<<<(2 * HID * DFFv + 255) / 256, 256>>>(W1, w1r, 2 * HID * DFFv);
        round_copy_kernel<<<(2 * DFFv * HID + 255) / 256, 256>>>(W2, w2r, 2 * DFFv * HID);
        int total = (HID + 1) * (WA_COLS + WB_COLS);
        build_weights_kernel<<<(total + 255) / 256, 256>>>(Wk, bk, Wq, bq, Wv, bv, ratt, rmsg);
    }
    cudaEventRecord(evP, 0);

    // ---- projection GEMMs (fp16 outputs): A on default, B on s2 ----
    {
        OutSegs sa;
        sa.p[0] = (float*)qA; sa.p[1] = (float*)kp[0]; sa.p[2] = (float*)vp[0];
        sa.p[3] = (float*)kp[2]; sa.p[4] = (float*)vp[2];
        sgemm_seg(hr[0], wA, wA + (size_t)HID * WA_COLS, nullptr, sa, HID, M, HID, WA_COLS, 0, 0, 1, 0);
        cudaStreamWaitEvent(s2, evP, 0);
        OutSegs sb;
        sb.p[0] = (float*)qB; sb.p[1] = (float*)kp[1]; sb.p[2] = (float*)vp[1];
        sb.p[3] = nullptr; sb.p[4] = nullptr;
        sgemm_seg(hr[1], wB, wB + (size_t)HID * WB_COLS, nullptr, sb, HID, M, HID, WB_COLS, 0, 0, 1, s2);
        cudaEventRecord(evB, s2);
    }
    cudaStreamWaitEvent(0, evB, 0);
    cudaEventRecord(evG, 0);

    // ---- side stream: attn r0 (-> t1) + full type-b chain ----
    cudaStreamWaitEvent(s1, evG, 0);
    node_attn_kernel<<<(M * 32 + 255) / 256, 256, 0, s1>>>(
        kp[0], vp[0], qB, off[0], csr[0], pri + 0 * NH, t1, M);
    {
        OutSegs sx; sx.p[0] = X[1]; sx.p[1] = sx.p[2] = sx.p[3] = sx.p[4] = nullptr;
        sgemm_seg(t1, war + (size_t)1 * HID * HID, ba + 1 * HID, h_b, sx, HID, M, HID, HID, 0, 0, 0, s1);
        ln_kernel<<<(M + 7) / 8, 256, 0, s1>>>(X[1], gam + 1 * HID, bet + 1 * HID, M);
        OutSegs sf; sf.p[0] = FF[1]; sf.p[1] = FF[1] + 128; sf.p[2] = FF[1] + 256; sf.p[3] = FF[1] + 384; sf.p[4] = nullptr;
        sgemm_seg(X[1], w1r + (size_t)1 * HID * DFFv, b1 + 1 * DFFv, nullptr, sf, DFFv, M, HID, DFFv, 1, 1, 0, s1);
        OutSegs so; so.p[0] = out + (size_t)1 * M * HID; so.p[1] = so.p[2] = so.p[3] = so.p[4] = nullptr;
        sgemm_seg(FF[1], w2r + (size_t)1 * DFFv * HID, b2 + 1 * HID, nullptr, so, HID, M, DFFv, HID, 0, 0, 0, s1);
    }
    cudaEventRecord(evE, s1);

    // ---- default stream: dual attn (r1 + r2 -> t0) + type-a chain ----
    cudaStreamWaitEvent(0, evJ, 0);
    node_attn_dual_kernel<<<(M * 32 + 255) / 256, 256>>>(
        kp[1], vp[1], kp[2], vp[2], qA,
        off[1], csr[1], off[2], csr[2],
        pri + 1 * NH, pri + 2 * NH, t0, M);
    {
        OutSegs sx; sx.p[0] = X[0]; sx.p[1] = sx.p[2] = sx.p[3] = sx.p[4] = nullptr;
        sgemm_seg(t0, war + (size_t)0 * HID * HID, ba + 0 * HID, h_a, sx, HID, M, HID, HID, 0, 0, 0, 0);
        ln_kernel<<<(M + 7) / 8, 256>>>(X[0], gam + 0 * HID, bet + 0 * HID, M);
        OutSegs sf; sf.p[0] = FF[0]; sf.p[1] = FF[0] + 128; sf.p[2] = FF[0] + 256; sf.p[3] = FF[0] + 384; sf.p[4] = nullptr;
        sgemm_seg(X[0], w1r + (size_t)0 * HID * DFFv, b1 + 0 * DFFv, nullptr, sf, DFFv, M, HID, DFFv, 1, 1, 0, 0);
        OutSegs so; so.p[0] = out + (size_t)0 * M * HID; so.p[1] = so.p[2] = so.p[3] = so.p[4] = nullptr;
        sgemm_seg(FF[0], w2r + (size_t)0 * DFFv * HID, b2 + 0 * HID, nullptr, so, HID, M, DFFv, HID, 0, 0, 0, 0);
    }

    // ---- join side stream ----
    cudaStreamWaitEvent(0, evE, 0);
}

// round 17
// speedup vs baseline: 1.2995x; 1.2995x over previous
#include <cuda_runtime.h>
#include <cuda_fp16.h>
#include <cstdint>
#include <cstddef>

#define Nn 100000
#define En 500000
#define HID 128
#define NH 8
#define DKv 16
#define DFFv 512
#define WA_COLS 640
#define WB_COLS 384
#define SCAN_TB 1024
#define SCAN_NBLK ((Nn + SCAN_TB - 1) / SCAN_TB)

// ---------------- scratch (device globals; allocation-free) ----------------
__device__ __half g_qA[(size_t)Nn * HID];
__device__ __half g_qB[(size_t)Nn * HID];
__device__ __half g_kp[3][(size_t)Nn * HID];
__device__ __half g_vp[3][(size_t)Nn * HID];
__device__ float g_t[2][(size_t)Nn * HID];
__device__ float g_x[2][(size_t)Nn * HID];
__device__ float g_ff[2][(size_t)Nn * DFFv];
__device__ float g_hr[2][(size_t)Nn * HID];        // rounded copies of h_a/h_b
__device__ int g_cnt[Nn];
__device__ int g_incl[Nn];
__device__ int g_tsum[SCAN_NBLK];
__device__ int g_toff[SCAN_NBLK];
__device__ int g_off[3][Nn + 1];
__device__ int g_off2[3][Nn];
__device__ int g_csr[3][En];
__device__ float g_wA[(HID + 1) * WA_COLS];        // row 128 = bias (unrounded)
__device__ float g_wB[(HID + 1) * WB_COLS];
__device__ float g_war[2 * HID * HID];             // rounded Wa
__device__ float g_w1r[2 * HID * DFFv];            // rounded W1
__device__ float g_w2r[2 * DFFv * HID];            // rounded W2
__device__ int g_is64;

struct OutSegs { float* p[5]; };

// ---------------- helpers ----------------
__device__ __forceinline__ uint32_t f2tf32(float x) {
    uint32_t u;
    asm("cvt.rna.tf32.f32 %0, %1;" : "=r"(u) : "f"(x));
    return u;
}
__device__ __forceinline__ float roundtf(float x) {
    return __uint_as_float(f2tf32(x));
}
__device__ __forceinline__ int ldidx(const void* p, int i) {
    return g_is64 ? (int)((const long long*)p)[i] : ((const int*)p)[i];
}
__device__ __forceinline__ float4 ldh4(const __half* p) {
    uint2 r = *reinterpret_cast<const uint2*>(p);
    __half2 h0 = *reinterpret_cast<__half2*>(&r.x);
    __half2 h1 = *reinterpret_cast<__half2*>(&r.y);
    float2 f0 = __half22float2(h0), f1 = __half22float2(h1);
    return make_float4(f0.x, f0.y, f1.x, f1.y);
}

__global__ void fill_i32(int* p, int v, int n) {
    int i = blockIdx.x * blockDim.x + threadIdx.x;
    if (i < n) p[i] = v;
}
__global__ void round_copy_kernel(const float* __restrict__ src, float* __restrict__ dst, int n) {
    int i = blockIdx.x * blockDim.x + threadIdx.x;
    if (i < n) dst[i] = roundtf(src[i]);
}

// Detect whether index buffers are int64 (odd 32-bit words == 0) or int32.
__global__ void detect_kernel(const unsigned* __restrict__ p) {
    if (blockIdx.x == 0 && threadIdx.x == 0) {
        int any = 0;
        for (int i = 1; i < 2048; i += 2) any |= (p[i] != 0u);
        g_is64 = !any;
    }
}

// ---------------- weight fusion prep (rounded weights, raw bias row) ----------------
__global__ void build_weights_kernel(
    const float* __restrict__ Wk, const float* __restrict__ bk,
    const float* __restrict__ Wq, const float* __restrict__ bq,
    const float* __restrict__ Wv, const float* __restrict__ bv,
    const float* __restrict__ att, const float* __restrict__ msg)
{
    int idx = blockIdx.x * blockDim.x + threadIdx.x;
    int total = (HID + 1) * (WA_COLS + WB_COLS);
    if (idx >= total) return;
    int isB = idx >= (HID + 1) * WA_COLS;
    int rem = isB ? idx - (HID + 1) * WA_COLS : idx;
    int cols = isB ? WB_COLS : WA_COLS;
    int i = rem / cols;          // 0..128 (128 = bias row)
    int c = rem % cols;
    int seg = c >> 7;
    int cl = c & 127;
    int h = cl >> 4, j = cl & 15;
    int ty = isB ? 1 : 0;
    float out;
    if (seg == 0) {
        out = (i < HID) ? Wq[((size_t)ty * HID + i) * HID + cl] : bq[ty * HID + cl];
    } else {
        int r = isB ? 1 : (seg <= 2 ? 0 : 2);
        int isV = (seg & 1) == 0;
        const float* W = isV ? Wv : Wk;
        const float* bb = isV ? bv : bk;
        const float* T = isV ? msg : att;
        const float* Th = T + ((size_t)(r * NH + h) * DKv) * DKv + j;
        float acc = 0.f;
        if (i < HID) {
            const float* Wr = W + ((size_t)ty * HID + i) * HID + h * DKv;
#pragma unroll
            for (int l = 0; l < DKv; l++) acc += Wr[l] * Th[(size_t)l * DKv];
        } else {
            const float* br = bb + ty * HID + h * DKv;
#pragma unroll
            for (int l = 0; l < DKv; l++) acc += br[l] * Th[(size_t)l * DKv];
        }
        out = acc;
    }
    if (i < HID) out = roundtf(out);
    if (isB) g_wB[(size_t)i * WB_COLS + c] = out;
    else     g_wA[(size_t)i * WA_COLS + c] = out;
}

// ---------------- TF32 GEMM: cp.async double-buffered (R15 form) ----------------
#define LDA 36
#define LDB 136
#define A_WORDS (128 * LDA)
#define B_WORDS (32 * LDB)
#define GEMM_SMEM_BYTES ((2 * (A_WORDS + B_WORDS)) * 4)

__device__ __forceinline__ void cp16(uint32_t dst, const void* src, bool valid) {
    int sz = valid ? 16 : 0;
    asm volatile("cp.async.cg.shared.global [%0], [%1], 16, %2;"
                 :: "r"(dst), "l"(src), "r"(sz) : "memory");
}
#define CP_COMMIT() asm volatile("cp.async.commit_group;" ::: "memory")
#define CP_WAIT(n)  asm volatile("cp.async.wait_group %0;" :: "n"(n) : "memory")

__global__ __launch_bounds__(256) void tf32gemm_kernel(
    const float* __restrict__ A, const float* __restrict__ B,
    const float* __restrict__ bias, const float* __restrict__ res,
    OutSegs segs, int segStride, int M, int K, int Nc,
    int reluOut, int roundOut, int halfOut)
{
    extern __shared__ uint32_t smem[];
    uint32_t sbase = (uint32_t)__cvta_generic_to_shared(smem);

    int tid = threadIdx.x;
    int warp = tid >> 5, lane = tid & 31;
    int g = lane >> 2, t = lane & 3;
    int wm = warp >> 2, wn = warp & 3;
    int rowTile = blockIdx.y * 128;
    int colTile = blockIdx.x * 128;
    float* Cb = segs.p[blockIdx.x];

    float c[4][4][4];
#pragma unroll
    for (int m = 0; m < 4; m++)
#pragma unroll
        for (int n = 0; n < 4; n++)
#pragma unroll
            for (int r = 0; r < 4; r++) c[m][n][r] = 0.f;

    int arow = tid >> 3;
    int acol4 = (tid & 7) * 4;
    int brow = tid >> 3;
    int bcol4 = (tid & 7) * 4;

    auto issueTile = [&](int k0, int buf) {
        uint32_t aBase = sbase + (uint32_t)buf * A_WORDS * 4;
        uint32_t bBase = sbase + (2 * A_WORDS + (uint32_t)buf * B_WORDS) * 4;
#pragma unroll
        for (int p = 0; p < 4; p++) {
            int r = arow + 32 * p;
            int gr = rowTile + r;
            cp16(aBase + (uint32_t)(r * LDA + acol4) * 4,
                 A + (size_t)gr * K + k0 + acol4, gr < M);
            int cc = bcol4 + 32 * p;
            cp16(bBase + (uint32_t)(brow * LDB + cc) * 4,
                 B + (size_t)(k0 + brow) * Nc + colTile + cc, true);
        }
    };

    int nit = K >> 5;
    issueTile(0, 0);
    CP_COMMIT();

    int cur = 0;
    for (int i = 0; i < nit; i++) {
        if (i + 1 < nit) {
            issueTile((i + 1) << 5, cur ^ 1);
            CP_COMMIT();
            CP_WAIT(1);
        } else {
            CP_WAIT(0);
        }
        __syncthreads();

        const uint32_t* Ac = smem + (size_t)cur * A_WORDS;
        const uint32_t* Bc = smem + 2 * A_WORDS + (size_t)cur * B_WORDS;
#pragma unroll
        for (int ks = 0; ks < 32; ks += 8) {
            uint32_t a[4][4], b[4][2];
#pragma unroll
            for (int m = 0; m < 4; m++) {
                int r = wm * 64 + m * 16 + g;
                a[m][0] = Ac[r * LDA + ks + t];
                a[m][1] = Ac[(r + 8) * LDA + ks + t];
                a[m][2] = Ac[r * LDA + ks + t + 4];
                a[m][3] = Ac[(r + 8) * LDA + ks + t + 4];
            }
#pragma unroll
            for (int n = 0; n < 4; n++) {
                int cc = wn * 32 + n * 8 + g;
                b[n][0] = Bc[(ks + t) * LDB + cc];
                b[n][1] = Bc[(ks + t + 4) * LDB + cc];
            }
#pragma unroll
            for (int m = 0; m < 4; m++)
#pragma unroll
                for (int n = 0; n < 4; n++) {
                    asm volatile(
                        "mma.sync.aligned.m16n8k8.row.col.f32.tf32.tf32.f32 "
                        "{%0,%1,%2,%3}, {%4,%5,%6,%7}, {%8,%9}, {%0,%1,%2,%3};"
                        : "+f"(c[m][n][0]), "+f"(c[m][n][1]),
                          "+f"(c[m][n][2]), "+f"(c[m][n][3])
                        : "r"(a[m][0]), "r"(a[m][1]), "r"(a[m][2]), "r"(a[m][3]),
                          "r"(b[n][0]), "r"(b[n][1]));
                }
        }
        __syncthreads();
        cur ^= 1;
    }

#pragma unroll
    for (int m = 0; m < 4; m++) {
        int row0 = rowTile + wm * 64 + m * 16 + g;
#pragma unroll
        for (int n = 0; n < 4; n++) {
            int cws = wn * 32 + n * 8 + 2 * t;
            int col = colTile + cws;
            float b0 = bias[col], b1 = bias[col + 1];
#pragma unroll
            for (int h = 0; h < 2; h++) {
                int row = row0 + 8 * h;
                if (row >= M) continue;
                size_t off = (size_t)row * segStride + cws;
                float v0 = c[m][n][2 * h + 0] + b0;
                float v1 = c[m][n][2 * h + 1] + b1;
                if (halfOut) {
                    __half2 hv = __floats2half2_rn(v0, v1);
                    *reinterpret_cast<__half2*>(reinterpret_cast<__half*>(Cb) + off) = hv;
                } else {
                    if (res) { v0 += res[off]; v1 += res[off + 1]; }
                    if (reluOut) { v0 = fmaxf(v0, 0.f); v1 = fmaxf(v1, 0.f); }
                    if (roundOut) { v0 = roundtf(v0); v1 = roundtf(v1); }
                    *reinterpret_cast<float2*>(Cb + off) = make_float2(v0, v1);
                }
            }
        }
    }
}

// ---------------- CSR build (coalesced 3-phase scan) ----------------
__global__ void hist_kernel(const void* __restrict__ dst, int* __restrict__ cnt, int E) {
    int i = blockIdx.x * blockDim.x + threadIdx.x;
    if (i < E) atomicAdd(&cnt[ldidx(dst, i)], 1);
}

__global__ __launch_bounds__(SCAN_TB) void scan1_kernel(
    const int* __restrict__ cnt, int* __restrict__ incl, int* __restrict__ tsum, int Nv)
{
    __shared__ int sh[SCAN_TB];
    int i = blockIdx.x * SCAN_TB + threadIdx.x;
    int v = (i < Nv) ? cnt[i] : 0;
    sh[threadIdx.x] = v;
    __syncthreads();
#pragma unroll
    for (int d = 1; d < SCAN_TB; d <<= 1) {
        int u = (threadIdx.x >= d) ? sh[threadIdx.x - d] : 0;
        __syncthreads();
        sh[threadIdx.x] += u;
        __syncthreads();
    }
    if (i < Nv) incl[i] = sh[threadIdx.x];
    if (threadIdx.x == SCAN_TB - 1) tsum[blockIdx.x] = sh[SCAN_TB - 1];
}

__global__ __launch_bounds__(128) void scan2_kernel(
    const int* __restrict__ tsum, int* __restrict__ toff, int nb)
{
    __shared__ int sh[SCAN_NBLK];
    if (threadIdx.x == 0) {
        int run = 0;
        for (int b = 0; b < nb; b++) { sh[b] = run; run += tsum[b]; }
    }
    __syncthreads();
    for (int b = threadIdx.x; b < nb; b += 128) toff[b] = sh[b];
}

__global__ void scan3_kernel(
    const int* __restrict__ cnt, const int* __restrict__ incl,
    const int* __restrict__ toff, int* __restrict__ off, int* __restrict__ off2,
    int Nv, int Etot)
{
    int i = blockIdx.x * blockDim.x + threadIdx.x;
    if (i < Nv) {
        int e = toff[i >> 10] + incl[i] - cnt[i];
        off[i] = e;
        off2[i] = e;
    }
    if (i == 0) off[Nv] = Etot;
}

__global__ void scatter_kernel(const void* __restrict__ src, const void* __restrict__ dst,
                               int* __restrict__ off2, int* __restrict__ csr, int E) {
    int i = blockIdx.x * blockDim.x + threadIdx.x;
    if (i >= E) return;
    int pos = atomicAdd(&off2[ldidx(dst, i)], 1);
    csr[pos] = ldidx(src, i);
}

// ---------------- single-relation attention (fp16 operands), relu+round out ----------------
__global__ __launch_bounds__(256) void node_attn_kernel(
    const __half* __restrict__ KP, const __half* __restrict__ VP,
    const __half* __restrict__ Q,
    const int* __restrict__ off, const int* __restrict__ csr,
    const float* __restrict__ pri,
    float* __restrict__ T, int Nv)
{
    int node = (blockIdx.x * blockDim.x + threadIdx.x) >> 5;
    int lane = threadIdx.x & 31;
    if (node >= Nv) return;
    int h = lane >> 2;
    float prih = pri[h] * 0.25f;

    float4 q = ldh4(Q + (size_t)node * HID + lane * 4);
    int s0 = off[node], s1 = off[node + 1];

    float m = -3.4e38f, z = 0.f;
    float4 acc = make_float4(0.f, 0.f, 0.f, 0.f);

    for (int slot = s0; slot < s1; slot++) {
        int sa = csr[slot];
        float4 ka = ldh4(KP + (size_t)sa * HID + lane * 4);
        float4 va = ldh4(VP + (size_t)sa * HID + lane * 4);
        float pa = q.x * ka.x + q.y * ka.y + q.z * ka.z + q.w * ka.w;
        pa += __shfl_xor_sync(0xffffffffu, pa, 1);
        pa += __shfl_xor_sync(0xffffffffu, pa, 2);
        float sca = pa * prih;
        float mn = fmaxf(m, sca);
        float corr = __expf(m - mn);
        float ea = __expf(sca - mn);
        z = z * corr + ea;
        acc.x = acc.x * corr + va.x * ea;
        acc.y = acc.y * corr + va.y * ea;
        acc.z = acc.z * corr + va.z * ea;
        acc.w = acc.w * corr + va.w * ea;
        m = mn;
    }
    float inv = (z > 0.f) ? (1.f / z) : 0.f;
    float* tp = T + (size_t)node * HID + lane * 4;
    float4 o;
    o.x = roundtf(fmaxf(acc.x * inv, 0.f));
    o.y = roundtf(fmaxf(acc.y * inv, 0.f));
    o.z = roundtf(fmaxf(acc.z * inv, 0.f));
    o.w = roundtf(fmaxf(acc.w * inv, 0.f));
    *reinterpret_cast<float4*>(tp) = o;
}

// ---------------- dual-relation attention: r1 + r2 -> relu(round(sum)) ----------------
__global__ __launch_bounds__(256) void node_attn_dual_kernel(
    const __half* __restrict__ KP1, const __half* __restrict__ VP1,
    const __half* __restrict__ KP2, const __half* __restrict__ VP2,
    const __half* __restrict__ Q,
    const int* __restrict__ off1, const int* __restrict__ csr1,
    const int* __restrict__ off2, const int* __restrict__ csr2,
    const float* __restrict__ pri1, const float* __restrict__ pri2,
    float* __restrict__ T, int Nv)
{
    int node = (blockIdx.x * blockDim.x + threadIdx.x) >> 5;
    int lane = threadIdx.x & 31;
    if (node >= Nv) return;
    int h = lane >> 2;

    float4 q = ldh4(Q + (size_t)node * HID + lane * 4);
    float4 tot = make_float4(0.f, 0.f, 0.f, 0.f);

    {
        float prih = pri1[h] * 0.25f;
        int s0 = off1[node], s1 = off1[node + 1];
        float m = -3.4e38f, z = 0.f;
        float4 acc = make_float4(0.f, 0.f, 0.f, 0.f);
        for (int slot = s0; slot < s1; slot++) {
            int sa = csr1[slot];
            float4 ka = ldh4(KP1 + (size_t)sa * HID + lane * 4);
            float4 va = ldh4(VP1 + (size_t)sa * HID + lane * 4);
            float pa = q.x * ka.x + q.y * ka.y + q.z * ka.z + q.w * ka.w;
            pa += __shfl_xor_sync(0xffffffffu, pa, 1);
            pa += __shfl_xor_sync(0xffffffffu, pa, 2);
            float sca = pa * prih;
            float mn = fmaxf(m, sca);
            float corr = __expf(m - mn);
            float ea = __expf(sca - mn);
            z = z * corr + ea;
            acc.x = acc.x * corr + va.x * ea;
            acc.y = acc.y * corr + va.y * ea;
            acc.z = acc.z * corr + va.z * ea;
            acc.w = acc.w * corr + va.w * ea;
            m = mn;
        }
        float inv = (z > 0.f) ? (1.f / z) : 0.f;
        tot.x += acc.x * inv; tot.y += acc.y * inv;
        tot.z += acc.z * inv; tot.w += acc.w * inv;
    }
    {
        float prih = pri2[h] * 0.25f;
        int s0 = off2[node], s1 = off2[node + 1];
        float m = -3.4e38f, z = 0.f;
        float4 acc = make_float4(0.f, 0.f, 0.f, 0.f);
        for (int slot = s0; slot < s1; slot++) {
            int sa = csr2[slot];
            float4 ka = ldh4(KP2 + (size_t)sa * HID + lane * 4);
            float4 va = ldh4(VP2 + (size_t)sa * HID + lane * 4);
            float pa = q.x * ka.x + q.y * ka.y + q.z * ka.z + q.w * ka.w;
            pa += __shfl_xor_sync(0xffffffffu, pa, 1);
            pa += __shfl_xor_sync(0xffffffffu, pa, 2);
            float sca = pa * prih;
            float mn = fmaxf(m, sca);
            float corr = __expf(m - mn);
            float ea = __expf(sca - mn);
            z = z * corr + ea;
            acc.x = acc.x * corr + va.x * ea;
            acc.y = acc.y * corr + va.y * ea;
            acc.z = acc.z * corr + va.z * ea;
            acc.w = acc.w * corr + va.w * ea;
            m = mn;
        }
        float inv = (z > 0.f) ? (1.f / z) : 0.f;
        tot.x += acc.x * inv; tot.y += acc.y * inv;
        tot.z += acc.z * inv; tot.w += acc.w * inv;
    }

    float* tp = T + (size_t)node * HID + lane * 4;
    float4 o;
    o.x = roundtf(fmaxf(tot.x, 0.f));
    o.y = roundtf(fmaxf(tot.y, 0.f));
    o.z = roundtf(fmaxf(tot.z, 0.f));
    o.w = roundtf(fmaxf(tot.w, 0.f));
    *reinterpret_cast<float4*>(tp) = o;
}

// ---------------- LayerNorm over 128 (warp per row, in-place, rounded output) ----------------
__global__ __launch_bounds__(256) void ln_kernel(
    float* __restrict__ X, const float* __restrict__ gamma,
    const float* __restrict__ beta, int M)
{
    int warp = (blockIdx.x * blockDim.x + threadIdx.x) >> 5;
    int lane = threadIdx.x & 31;
    if (warp >= M) return;
    float4 v = *reinterpret_cast<float4*>(X + (size_t)warp * HID + lane * 4);
    float sum = v.x + v.y + v.z + v.w;
    float sq = v.x * v.x + v.y * v.y + v.z * v.z + v.w * v.w;
#pragma unroll
    for (int o = 16; o > 0; o >>= 1) {
        sum += __shfl_xor_sync(0xffffffffu, sum, o);
        sq += __shfl_xor_sync(0xffffffffu, sq, o);
    }
    float mu = sum * (1.f / 128.f);
    float var = sq * (1.f / 128.f) - mu * mu;
    float inv = rsqrtf(var + 1e-5f);
    float4 g = *reinterpret_cast<const float4*>(gamma + lane * 4);
    float4 b = *reinterpret_cast<const float4*>(beta + lane * 4);
    v.x = roundtf((v.x - mu) * inv * g.x + b.x);
    v.y = roundtf((v.y - mu) * inv * g.y + b.y);
    v.z = roundtf((v.z - mu) * inv * g.z + b.z);
    v.w = roundtf((v.w - mu) * inv * g.w + b.w);
    *reinterpret_cast<float4*>(X + (size_t)warp * HID + lane * 4) = v;
}

// ---------------- host ----------------
static void sgemm_seg(const float* A, const float* B, const float* bias, const float* res,
                      OutSegs segs, int segStride, int M, int K, int Nc,
                      int reluOut, int roundOut, int halfOut, cudaStream_t st)
{
    dim3 grid(Nc / 128, (M + 127) / 128);
    tf32gemm_kernel<<<grid, 256, GEMM_SMEM_BYTES, st>>>(
        A, B, bias, res, segs, segStride, M, K, Nc, reluOut, roundOut, halfOut);
}

template <typename T>
static T* symaddr(const void* sym) {
    void* p = nullptr;
    cudaGetSymbolAddress(&p, sym);
    return (T*)p;
}

extern "C" void kernel_launch(void* const* d_in, const int* in_sizes, int n_in,
                              void* d_out, int out_size)
{
    const float* h_a  = (const float*)d_in[0];
    const float* h_b  = (const float*)d_in[1];
    const float* Wk   = (const float*)d_in[2];
    const float* bk   = (const float*)d_in[3];
    const float* Wq   = (const float*)d_in[4];
    const float* bq   = (const float*)d_in[5];
    const float* Wv   = (const float*)d_in[6];
    const float* bv   = (const float*)d_in[7];
    const float* Wa   = (const float*)d_in[8];
    const float* ba   = (const float*)d_in[9];
    const float* gam  = (const float*)d_in[10];
    const float* bet  = (const float*)d_in[11];
    const float* W1   = (const float*)d_in[12];
    const float* b1   = (const float*)d_in[13];
    const float* W2   = (const float*)d_in[14];
    const float* b2   = (const float*)d_in[15];
    const float* pri  = (const float*)d_in[16];
    const float* ratt = (const float*)d_in[17];
    const float* rmsg = (const float*)d_in[18];

    int M = in_sizes[0] / HID;
    int Ec[3] = { in_sizes[19], in_sizes[21], in_sizes[23] };
    float* out = (float*)d_out;

    __half* qA = symaddr<__half>(&g_qA);
    __half* qB = symaddr<__half>(&g_qB);
    __half* kpB = symaddr<__half>(&g_kp);
    __half* vpB = symaddr<__half>(&g_vp);
    __half* kp[3] = { kpB, kpB + (size_t)Nn * HID, kpB + 2 * (size_t)Nn * HID };
    __half* vp[3] = { vpB, vpB + (size_t)Nn * HID, vpB + 2 * (size_t)Nn * HID };
    float* t0 = symaddr<float>(&g_t);  float* t1 = t0 + (size_t)Nn * HID;
    float* Xb = symaddr<float>(&g_x);
    float* FFb = symaddr<float>(&g_ff);
    float* X[2]  = { Xb, Xb + (size_t)Nn * HID };
    float* FF[2] = { FFb, FFb + (size_t)Nn * DFFv };
    float* hrB = symaddr<float>(&g_hr);
    float* hr[2] = { hrB, hrB + (size_t)Nn * HID };
    int* cnt  = symaddr<int>(&g_cnt);
    int* incl = symaddr<int>(&g_incl);
    int* tsum = symaddr<int>(&g_tsum);
    int* toff = symaddr<int>(&g_toff);
    int* offB = symaddr<int>(&g_off);
    int* off2B = symaddr<int>(&g_off2);
    int* csrB = symaddr<int>(&g_csr);
    int* off[3]  = { offB, offB + (Nn + 1), offB + 2 * (Nn + 1) };
    int* off2[3] = { off2B, off2B + Nn, off2B + 2 * Nn };
    int* csr[3]  = { csrB, csrB + En, csrB + 2 * En };
    float* wA = symaddr<float>(&g_wA);
    float* wB = symaddr<float>(&g_wB);
    float* war = symaddr<float>(&g_war);
    float* w1r = symaddr<float>(&g_w1r);
    float* w2r = symaddr<float>(&g_w2r);

    static cudaStream_t s1 = nullptr, s2 = nullptr;
    static cudaEvent_t evF = nullptr, evJ = nullptr, evG = nullptr, evE = nullptr;
    static cudaEvent_t evP = nullptr, evB = nullptr;
    if (!s1) {
        cudaStreamCreateWithFlags(&s1, cudaStreamNonBlocking);
        cudaStreamCreateWithFlags(&s2, cudaStreamNonBlocking);
        cudaEventCreateWithFlags(&evF, cudaEventDisableTiming);
        cudaEventCreateWithFlags(&evJ, cudaEventDisableTiming);
        cudaEventCreateWithFlags(&evG, cudaEventDisableTiming);
        cudaEventCreateWithFlags(&evE, cudaEventDisableTiming);
        cudaEventCreateWithFlags(&evP, cudaEventDisableTiming);
        cudaEventCreateWithFlags(&evB, cudaEventDisableTiming);
        cudaFuncSetAttribute(tf32gemm_kernel,
                             cudaFuncAttributeMaxDynamicSharedMemorySize,
                             GEMM_SMEM_BYTES);
    }

    // ---- s2 (no deps): round h_b and chain weights, concurrent with head ----
    {
        int nh = M * HID;
        round_copy_kernel<<<(nh + 255) / 256, 256, 0, s2>>>(h_b, hr[1], nh);
        round_copy_kernel<<<(2 * HID * HID + 255) / 256, 256, 0, s2>>>(Wa, war, 2 * HID * HID);
        round_copy_kernel<<<(2 * HID * DFFv + 255) / 256, 256, 0, s2>>>(W1, w1r, 2 * HID * DFFv);
        round_copy_kernel<<<(2 * DFFv * HID + 255) / 256, 256, 0, s2>>>(W2, w2r, 2 * DFFv * HID);
    }

    // ---- default: detect -> fork CSR on s1; round h_a; build weights ----
    detect_kernel<<<1, 32>>>((const unsigned*)d_in[19]);
    cudaEventRecord(evF, 0);
    cudaStreamWaitEvent(s1, evF, 0);
    for (int r = 0; r < 3; r++) {
        int E = Ec[r];
        fill_i32<<<(Nn + 255) / 256, 256, 0, s1>>>(cnt, 0, Nn);
        hist_kernel<<<(E + 255) / 256, 256, 0, s1>>>(d_in[20 + 2 * r], cnt, E);
        scan1_kernel<<<SCAN_NBLK, SCAN_TB, 0, s1>>>(cnt, incl, tsum, M);
        scan2_kernel<<<1, 128, 0, s1>>>(tsum, toff, (M + SCAN_TB - 1) / SCAN_TB);
        scan3_kernel<<<(Nn + 255) / 256, 256, 0, s1>>>(cnt, incl, toff, off[r], off2[r], M, E);
        scatter_kernel<<<(E + 255) / 256, 256, 0, s1>>>(d_in[19 + 2 * r], d_in[20 + 2 * r], off2[r], csr[r], E);
        if (r == 2) cudaEventRecord(evJ, s1);
    }
    {
        int nh = M * HID;
        round_copy_kernel<<<(nh + 255) / 256, 256>>>(h_a, hr[0], nh);
        int total = (HID + 1) * (WA_COLS + WB_COLS);
        build_weights_kernel<<<(total + 255) / 256, 256>>>(Wk, bk, Wq, bq, Wv, bv, ratt, rmsg);
    }
    cudaEventRecord(evP, 0);

    // ---- projection GEMMs (fp16 outputs): A on default, B on s2 ----
    {
        OutSegs sa;
        sa.p[0] = (float*)qA; sa.p[1] = (float*)kp[0]; sa.p[2] = (float*)vp[0];
        sa.p[3] = (float*)kp[2]; sa.p[4] = (float*)vp[2];
        sgemm_seg(hr[0], wA, wA + (size_t)HID * WA_COLS, nullptr, sa, HID, M, HID, WA_COLS, 0, 0, 1, 0);
        cudaStreamWaitEvent(s2, evP, 0);   // s2 already rounded hr[1]; needs wB from build_weights
        OutSegs sb;
        sb.p[0] = (float*)qB; sb.p[1] = (float*)kp[1]; sb.p[2] = (float*)vp[1];
        sb.p[3] = nullptr; sb.p[4] = nullptr;
        sgemm_seg(hr[1], wB, wB + (size_t)HID * WB_COLS, nullptr, sb, HID, M, HID, WB_COLS, 0, 0, 1, s2);
        cudaEventRecord(evB, s2);
    }
    cudaStreamWaitEvent(0, evB, 0);
    cudaEventRecord(evG, 0);

    // ---- side stream: attn r0 (-> t1) + full type-b chain ----
    cudaStreamWaitEvent(s1, evG, 0);
    node_attn_kernel<<<(M * 32 + 255) / 256, 256, 0, s1>>>(
        kp[0], vp[0], qB, off[0], csr[0], pri + 0 * NH, t1, M);
    {
        OutSegs sx; sx.p[0] = X[1]; sx.p[1] = sx.p[2] = sx.p[3] = sx.p[4] = nullptr;
        sgemm_seg(t1, war + (size_t)1 * HID * HID, ba + 1 * HID, h_b, sx, HID, M, HID, HID, 0, 0, 0, s1);
        ln_kernel<<<(M + 7) / 8, 256, 0, s1>>>(X[1], gam + 1 * HID, bet + 1 * HID, M);
        OutSegs sf; sf.p[0] = FF[1]; sf.p[1] = FF[1] + 128; sf.p[2] = FF[1] + 256; sf.p[3] = FF[1] + 384; sf.p[4] = nullptr;
        sgemm_seg(X[1], w1r + (size_t)1 * HID * DFFv, b1 + 1 * DFFv, nullptr, sf, DFFv, M, HID, DFFv, 1, 1, 0, s1);
        OutSegs so; so.p[0] = out + (size_t)1 * M * HID; so.p[1] = so.p[2] = so.p[3] = so.p[4] = nullptr;
        sgemm_seg(FF[1], w2r + (size_t)1 * DFFv * HID, b2 + 1 * HID, nullptr, so, HID, M, DFFv, HID, 0, 0, 0, s1);
    }
    cudaEventRecord(evE, s1);

    // ---- default stream: dual attn (r1 + r2 -> t0) + type-a chain ----
    cudaStreamWaitEvent(0, evJ, 0);
    node_attn_dual_kernel<<<(M * 32 + 255) / 256, 256>>>(
        kp[1], vp[1], kp[2], vp[2], qA,
        off[1], csr[1], off[2], csr[2],
        pri + 1 * NH, pri + 2 * NH, t0, M);
    {
        OutSegs sx; sx.p[0] = X[0]; sx.p[1] = sx.p[2] = sx.p[3] = sx.p[4] = nullptr;
        sgemm_seg(t0, war + (size_t)0 * HID * HID, ba + 0 * HID, h_a, sx, HID, M, HID, HID, 0, 0, 0, 0);
        ln_kernel<<<(M + 7) / 8, 256>>>(X[0], gam + 0 * HID, bet + 0 * HID, M);
        OutSegs sf; sf.p[0] = FF[0]; sf.p[1] = FF[0] + 128; sf.p[2] = FF[0] + 256; sf.p[3] = FF[0] + 384; sf.p[4] = nullptr;
        sgemm_seg(X[0], w1r + (size_t)0 * HID * DFFv, b1 + 0 * DFFv, nullptr, sf, DFFv, M, HID, DFFv, 1, 1, 0, 0);
        OutSegs so; so.p[0] = out + (size_t)0 * M * HID; so.p[1] = so.p[2] = so.p[3] = so.p[4] = nullptr;
        sgemm_seg(FF[0], w2r + (size_t)0 * DFFv * HID, b2 + 0 * HID, nullptr, so, HID, M, DFFv, HID, 0, 0, 0, 0);
    }

    // ---- join side stream ----
    cudaStreamWaitEvent(0, evE, 0);
}